// round 5
// baseline (speedup 1.0000x reference)
#include <cuda_runtime.h>
#include <math.h>
#include <stdint.h>

// ---------------- problem constants ----------------
#define Lq     2048
#define HIDm   4096
#define Hh     128
#define Pp     64
#define Nn     128
#define Gg     8
#define Kk     4
#define CSz    256
#define NC     8            // L / CS
#define INTERC 8192         // H*P
#define CONVC  10240        // INTER + 2*G*N
#define PROJC  18560        // INTER + CONV + H
#define GSZ    1024         // INTER / G
#define EPSf   1e-5f

// ---------------- scratch (static device globals; no allocation) ----------------
__device__ float d_proj[(size_t)Lq * PROJC];
__device__ float d_xbc [(size_t)Lq * CONVC];
__device__ float d_dt  [(size_t)Lq * Hh];
__device__ float d_cum [(size_t)Lq * Hh];
__device__ float d_y   [(size_t)Lq * INTERC];
__device__ float d_st  [(size_t)NC * Hh * Pp * Nn];
__device__ float d_prev[(size_t)NC * Hh * Pp * Nn];
__device__ float d_g   [(size_t)Lq * INTERC];
// pre-converted tf32 operands
__device__ float d_wa  [(size_t)Lq * HIDm];
__device__ float d_wb1 [(size_t)PROJC * HIDm];
__device__ float d_wb2 [(size_t)HIDm * INTERC];

__device__ __forceinline__ uint32_t smem_u32(const void* p) {
    return (uint32_t)__cvta_generic_to_shared(p);
}
__device__ __forceinline__ void cp16(uint32_t dst, const void* src) {
    asm volatile("cp.async.cg.shared.global [%0], [%1], 16;\n" :: "r"(dst), "l"(src));
}
__device__ __forceinline__ uint32_t f2tf32(float x) {
    uint32_t r;
    asm("cvt.rna.tf32.f32 %0, %1;" : "=r"(r) : "f"(x));
    return r;
}
__device__ __forceinline__ void mma_tf32(float* c, const uint32_t* a, const uint32_t* b) {
    asm volatile(
        "mma.sync.aligned.m16n8k8.row.col.f32.tf32.tf32.f32 "
        "{%0,%1,%2,%3}, {%4,%5,%6,%7}, {%8,%9}, {%0,%1,%2,%3};"
        : "+f"(c[0]), "+f"(c[1]), "+f"(c[2]), "+f"(c[3])
        : "r"(a[0]), "r"(a[1]), "r"(a[2]), "r"(a[3]), "r"(b[0]), "r"(b[1]));
}

// ---------------- tf32 pre-convert (elementwise, float4) ----------------
__global__ void __launch_bounds__(256)
cvt_tf32_k(const float4* __restrict__ in, float4* __restrict__ outp, int n4) {
    int i = blockIdx.x * 256 + threadIdx.x;
    if (i >= n4) return;
    float4 v = in[i];
    v.x = __uint_as_float(f2tf32(v.x));
    v.y = __uint_as_float(f2tf32(v.y));
    v.z = __uint_as_float(f2tf32(v.z));
    v.w = __uint_as_float(f2tf32(v.w));
    outp[i] = v;
}

// =====================================================================
//  tf32 mma.sync GEMM: C[M,Ncols] = A[M,K] @ B[Ncols,K]^T
//  A/B pre-rounded to tf32. CTA tile 256x128 (M x N), BK=32, 256 thr,
//  8 warps (4m x 2n, 64x64 each), 3-stage cp.async ring, ONE sync/chunk.
// =====================================================================
#define BMt 256
#define BNt 128
#define BKt 32
#define PADk 36
#define STAGE_F ((BMt + BNt) * PADk)          // 13824 floats / stage
#define GM_SMEM (3 * STAGE_F * 4)             // 165888 bytes

__device__ __forceinline__ void gemm_mma_body(const float* __restrict__ A,
                                              const float* __restrict__ B,
                                              float* __restrict__ C,
                                              int Ncols, int K) {
    extern __shared__ float smf[];
    const uint32_t sbase = smem_u32(smf);
    const int tid = threadIdx.x, wid = tid >> 5, lane = tid & 31;
    const int g = lane >> 2, q = lane & 3;
    const int m0 = blockIdx.x * BMt;          // x = m -> wave keeps A L2-resident
    const int n0 = blockIdx.y * BNt;
    const int wm = (wid >> 1) * 64;
    const int wn = (wid & 1) * 64;
    const int nk = K / BKt;

    float acc[4][8][4];
#pragma unroll
    for (int i = 0; i < 4; ++i)
#pragma unroll
        for (int j = 0; j < 8; ++j)
#pragma unroll
            for (int r = 0; r < 4; ++r) acc[i][j][r] = 0.f;

    auto load_stage = [&](int c) {
        const int s = c % 3;
        const int k0 = c * BKt;
        const uint32_t abase = sbase + s * STAGE_F * 4;
        const uint32_t bbase = abase + BMt * PADk * 4;
#pragma unroll
        for (int i = 0; i < 8; ++i) {         // A: 256 rows x 8 float4
            int t = tid + i * 256;
            int r = t >> 3, qq = t & 7;
            cp16(abase + (uint32_t)(r * PADk + qq * 4) * 4,
                 A + (size_t)(m0 + r) * K + k0 + qq * 4);
        }
#pragma unroll
        for (int i = 0; i < 4; ++i) {         // B: 128 rows x 8 float4
            int t = tid + i * 256;
            int r = t >> 3, qq = t & 7;
            cp16(bbase + (uint32_t)(r * PADk + qq * 4) * 4,
                 B + (size_t)(n0 + r) * K + k0 + qq * 4);
        }
        asm volatile("cp.async.commit_group;");
    };

    load_stage(0);
    load_stage(1);

    for (int c = 0; c < nk; ++c) {
        if (c + 1 < nk) {
            asm volatile("cp.async.wait_group 1;");
        } else {
            asm volatile("cp.async.wait_group 0;");
        }
        __syncthreads();   // all warps see buffer c; all warps done with compute(c-1)

        if (c + 2 < nk) load_stage(c + 2);    // writes (c+2)%3 == (c-1)%3, now free

        const float* as = smf + (c % 3) * STAGE_F;
        const float* bs = as + BMt * PADk;

#pragma unroll
        for (int ks = 0; ks < 4; ++ks) {
            const int kk = ks * 8;
            uint32_t af[4][4];
#pragma unroll
            for (int mi = 0; mi < 4; ++mi) {
                const float* ap = as + (wm + mi * 16 + g) * PADk + kk + q;
                af[mi][0] = __float_as_uint(ap[0]);
                af[mi][1] = __float_as_uint(ap[8 * PADk]);
                af[mi][2] = __float_as_uint(ap[4]);
                af[mi][3] = __float_as_uint(ap[8 * PADk + 4]);
            }
            uint32_t bf[8][2];
#pragma unroll
            for (int ni = 0; ni < 8; ++ni) {
                const float* bp = bs + (wn + ni * 8 + g) * PADk + kk + q;
                bf[ni][0] = __float_as_uint(bp[0]);
                bf[ni][1] = __float_as_uint(bp[4]);
            }
#pragma unroll
            for (int mi = 0; mi < 4; ++mi)
#pragma unroll
                for (int ni = 0; ni < 8; ++ni)
                    mma_tf32(acc[mi][ni], af[mi], bf[ni]);
        }
    }

#pragma unroll
    for (int mi = 0; mi < 4; ++mi) {
        const int r = m0 + wm + mi * 16 + g;
#pragma unroll
        for (int ni = 0; ni < 8; ++ni) {
            const int cb = n0 + wn + ni * 8 + 2 * q;
            *(float2*)(C + (size_t)r * Ncols + cb) =
                make_float2(acc[mi][ni][0], acc[mi][ni][1]);
            *(float2*)(C + (size_t)(r + 8) * Ncols + cb) =
                make_float2(acc[mi][ni][2], acc[mi][ni][3]);
        }
    }
}

__global__ void __launch_bounds__(256, 1)
gemm1_mma_k() { gemm_mma_body(d_wa, d_wb1, d_proj, PROJC, HIDm); }
__global__ void __launch_bounds__(256, 1)
gemm2_mma_k(float* __restrict__ C) { gemm_mma_body(d_g, d_wb2, C, HIDm, INTERC); }

// ---------------- depthwise causal conv (K=4) + SiLU ----------------
__global__ void __launch_bounds__(256)
conv_silu_k(const float* __restrict__ w, const float* __restrict__ b) {
    int c = blockIdx.x * 256 + threadIdx.x;
    int l = blockIdx.y;
    if (c >= CONVC) return;
    float acc = b[c];
#pragma unroll
    for (int k = 0; k < Kk; ++k) {
        int ls = l - (Kk - 1) + k;
        if (ls >= 0) acc += w[c * Kk + k] * d_proj[(size_t)ls * PROJC + INTERC + c];
    }
    d_xbc[(size_t)l * CONVC + c] = acc / (1.f + __expf(-acc));
}

// ---------------- dt softplus + per-chunk cumsum of dA ----------------
__global__ void __launch_bounds__(256)
dt_cum_k(const float* __restrict__ dt_bias, const float* __restrict__ A_log) {
    int h = blockIdx.x, c = blockIdx.y, t = threadIdx.x;
    int l = c * CSz + t;
    float x = d_proj[(size_t)l * PROJC + (INTERC + CONVC) + h] + dt_bias[h];
    float sp = fmaxf(x, 0.f) + log1pf(expf(-fabsf(x)));
    float dtv = fmaxf(sp, 0.f);
    float A = -expf(A_log[h]);
    __shared__ float s[CSz];
    s[t] = dtv * A;
    __syncthreads();
    for (int off = 1; off < CSz; off <<= 1) {
        float v = (t >= off) ? s[t - off] : 0.f;
        __syncthreads();
        s[t] += v;
        __syncthreads();
    }
    d_dt [(size_t)l * Hh + h] = dtv;
    d_cum[(size_t)l * Hh + h] = s[t];
}

// ---------------- intra-chunk: y_intra = (CB^T * Ldec * dt) @ x ----------------
#define IT_SMEM ((2 * 128 * 68 + 2 * 64 * 68 + 192) * 4)
__global__ void __launch_bounds__(256, 2)
ssd_intra_k() {
    extern __shared__ float sdyn[];
    float* CsT = sdyn;                 // [n][i]  128x68
    float* BsT = CsT + 128 * 68;       // [n][j]  128x68
    float* SsT = BsT + 128 * 68;       // [j][i]   64x68
    float* Xs  = SsT + 64 * 68;        // [j][p]   64x68
    float* cum_i = Xs + 64 * 68;
    float* cum_j = cum_i + 64;
    float* dtj   = cum_j + 64;

    const int it = blockIdx.x, h = blockIdx.y, c = blockIdx.z;
    const int g = h >> 4;
    const int tid = threadIdx.x;
    const int tx = tid & 15, ty = tid >> 4;

    const int li0 = c * CSz + it * 64;
    const int ccol = INTERC + Gg * Nn + g * Nn;
    const int bcol = INTERC + g * Nn;

#pragma unroll
    for (int rep = 0; rep < 2; ++rep) {
        int b = tid + rep * 256;
        int bi = (b & 15) * 4;
        int bn = (b >> 4) * 4;
        float4 r0 = *(const float4*)(&d_xbc[(size_t)(li0 + bi + 0) * CONVC + ccol + bn]);
        float4 r1 = *(const float4*)(&d_xbc[(size_t)(li0 + bi + 1) * CONVC + ccol + bn]);
        float4 r2 = *(const float4*)(&d_xbc[(size_t)(li0 + bi + 2) * CONVC + ccol + bn]);
        float4 r3 = *(const float4*)(&d_xbc[(size_t)(li0 + bi + 3) * CONVC + ccol + bn]);
        *(float4*)&CsT[(bn + 0) * 68 + bi] = make_float4(r0.x, r1.x, r2.x, r3.x);
        *(float4*)&CsT[(bn + 1) * 68 + bi] = make_float4(r0.y, r1.y, r2.y, r3.y);
        *(float4*)&CsT[(bn + 2) * 68 + bi] = make_float4(r0.z, r1.z, r2.z, r3.z);
        *(float4*)&CsT[(bn + 3) * 68 + bi] = make_float4(r0.w, r1.w, r2.w, r3.w);
    }
    if (tid < 64) cum_i[tid] = d_cum[(size_t)(li0 + tid) * Hh + h];

    float yacc[4][4];
#pragma unroll
    for (int i = 0; i < 4; ++i)
#pragma unroll
        for (int j = 0; j < 4; ++j) yacc[i][j] = 0.f;

    for (int jt = 0; jt <= it; ++jt) {
        const int lj0 = c * CSz + jt * 64;
        __syncthreads();
#pragma unroll
        for (int rep = 0; rep < 2; ++rep) {
            int b = tid + rep * 256;
            int bi = (b & 15) * 4;
            int bn = (b >> 4) * 4;
            float4 r0 = *(const float4*)(&d_xbc[(size_t)(lj0 + bi + 0) * CONVC + bcol + bn]);
            float4 r1 = *(const float4*)(&d_xbc[(size_t)(lj0 + bi + 1) * CONVC + bcol + bn]);
            float4 r2 = *(const float4*)(&d_xbc[(size_t)(lj0 + bi + 2) * CONVC + bcol + bn]);
            float4 r3 = *(const float4*)(&d_xbc[(size_t)(lj0 + bi + 3) * CONVC + bcol + bn]);
            *(float4*)&BsT[(bn + 0) * 68 + bi] = make_float4(r0.x, r1.x, r2.x, r3.x);
            *(float4*)&BsT[(bn + 1) * 68 + bi] = make_float4(r0.y, r1.y, r2.y, r3.y);
            *(float4*)&BsT[(bn + 2) * 68 + bi] = make_float4(r0.z, r1.z, r2.z, r3.z);
            *(float4*)&BsT[(bn + 3) * 68 + bi] = make_float4(r0.w, r1.w, r2.w, r3.w);
        }
#pragma unroll
        for (int rep = 0; rep < 4; ++rep) {
            int idx = tid + rep * 256;
            int r = idx >> 4, qq = idx & 15;
            *(float4*)&Xs[r * 68 + qq * 4] =
                *(const float4*)(&d_xbc[(size_t)(lj0 + r) * CONVC + h * Pp + qq * 4]);
        }
        if (tid < 64) {
            cum_j[tid] = d_cum[(size_t)(lj0 + tid) * Hh + h];
            dtj  [tid] = d_dt [(size_t)(lj0 + tid) * Hh + h];
        }
        __syncthreads();

        float sacc[4][4];
#pragma unroll
        for (int i = 0; i < 4; ++i)
#pragma unroll
            for (int j = 0; j < 4; ++j) sacc[i][j] = 0.f;
#pragma unroll 8
        for (int kk = 0; kk < 128; ++kk) {
            float4 a4 = *(const float4*)&CsT[kk * 68 + ty * 4];
            float4 b4 = *(const float4*)&BsT[kk * 68 + tx * 4];
            float a[4] = {a4.x, a4.y, a4.z, a4.w};
            float b[4] = {b4.x, b4.y, b4.z, b4.w};
#pragma unroll
            for (int i = 0; i < 4; ++i)
#pragma unroll
                for (int j = 0; j < 4; ++j) sacc[i][j] += a[i] * b[j];
        }
#pragma unroll
        for (int jj = 0; jj < 4; ++jj) {
            int gj = jt * 64 + tx * 4 + jj;
            float cjv = cum_j[tx * 4 + jj];
            float djv = dtj[tx * 4 + jj];
            float v[4];
#pragma unroll
            for (int ii = 0; ii < 4; ++ii) {
                int gi = it * 64 + ty * 4 + ii;
                v[ii] = (gi >= gj) ? sacc[ii][jj] * __expf(cum_i[ty * 4 + ii] - cjv) * djv : 0.f;
            }
            *(float4*)&SsT[(tx * 4 + jj) * 68 + ty * 4] = make_float4(v[0], v[1], v[2], v[3]);
        }
        __syncthreads();

#pragma unroll 8
        for (int kkj = 0; kkj < 64; ++kkj) {
            float4 a4 = *(const float4*)&SsT[kkj * 68 + ty * 4];
            float4 b4 = *(const float4*)&Xs[kkj * 68 + tx * 4];
            float a[4] = {a4.x, a4.y, a4.z, a4.w};
            float b[4] = {b4.x, b4.y, b4.z, b4.w};
#pragma unroll
            for (int i = 0; i < 4; ++i)
#pragma unroll
                for (int j = 0; j < 4; ++j) yacc[i][j] += a[i] * b[j];
        }
    }
#pragma unroll
    for (int i = 0; i < 4; ++i) {
        *(float4*)(&d_y[(size_t)(li0 + ty * 4 + i) * INTERC + h * Pp + tx * 4]) =
            make_float4(yacc[i][0], yacc[i][1], yacc[i][2], yacc[i][3]);
    }
}

// ---------------- chunk states: st[p][n] = sum_j w_j x[j][p] B[j][n] ----------------
__global__ void __launch_bounds__(256)
ssd_states_k() {
    const int h = blockIdx.x, c = blockIdx.y;
    const int g = h >> 4;
    const int tid = threadIdx.x;
    const int tx = tid & 15, ty = tid >> 4;

    __shared__ float Xs[32][68];
    __shared__ float Bsh[32][132];
    __shared__ float ws[32];

    float acc[4][8];
#pragma unroll
    for (int i = 0; i < 4; ++i)
#pragma unroll
        for (int j = 0; j < 8; ++j) acc[i][j] = 0.f;

    const float cum_last = d_cum[(size_t)(c * CSz + CSz - 1) * Hh + h];

    for (int j0 = 0; j0 < CSz; j0 += 32) {
        __syncthreads();
#pragma unroll
        for (int rep = 0; rep < 2; ++rep) {
            int idx = tid + rep * 256;
            int r = idx >> 4, q = idx & 15;
            *(float4*)&Xs[r][q * 4] =
                *(const float4*)(&d_xbc[(size_t)(c * CSz + j0 + r) * CONVC + h * Pp + q * 4]);
        }
#pragma unroll
        for (int rep = 0; rep < 4; ++rep) {
            int idx = tid + rep * 256;
            int r = idx >> 5, q = idx & 31;
            *(float4*)&Bsh[r][q * 4] =
                *(const float4*)(&d_xbc[(size_t)(c * CSz + j0 + r) * CONVC + INTERC + g * Nn + q * 4]);
        }
        if (tid < 32) {
            int l = c * CSz + j0 + tid;
            ws[tid] = d_dt[(size_t)l * Hh + h] * __expf(cum_last - d_cum[(size_t)l * Hh + h]);
        }
        __syncthreads();
#pragma unroll 4
        for (int j = 0; j < 32; ++j) {
            float w = ws[j];
            float4 a4 = *(const float4*)&Xs[j][ty * 4];
            float aw[4] = {a4.x * w, a4.y * w, a4.z * w, a4.w * w};
            float4 b0 = *(const float4*)&Bsh[j][tx * 8];
            float4 b1 = *(const float4*)&Bsh[j][tx * 8 + 4];
            float b[8] = {b0.x, b0.y, b0.z, b0.w, b1.x, b1.y, b1.z, b1.w};
#pragma unroll
            for (int i = 0; i < 4; ++i)
#pragma unroll
                for (int jn = 0; jn < 8; ++jn) acc[i][jn] += aw[i] * b[jn];
        }
    }
#pragma unroll
    for (int i = 0; i < 4; ++i) {
        size_t base = ((size_t)(c * Hh + h) * Pp + ty * 4 + i) * Nn + tx * 8;
        *(float4*)&d_st[base]     = make_float4(acc[i][0], acc[i][1], acc[i][2], acc[i][3]);
        *(float4*)&d_st[base + 4] = make_float4(acc[i][4], acc[i][5], acc[i][6], acc[i][7]);
    }
}

// ---------------- inter-chunk scan ----------------
__global__ void __launch_bounds__(256)
ssd_scan_k() {
    int idx = blockIdx.x * 256 + threadIdx.x;
    if (idx >= Hh * Pp * Nn) return;
    int h = idx / (Pp * Nn);
    float carry = 0.f;
#pragma unroll
    for (int c = 0; c < NC; ++c) {
        d_prev[(size_t)c * Hh * Pp * Nn + idx] = carry;
        float cdec = __expf(d_cum[(size_t)(c * CSz + CSz - 1) * Hh + h]);
        carry = cdec * carry + d_st[(size_t)c * Hh * Pp * Nn + idx];
    }
}

// ---------------- inter-chunk output + D*x ----------------
__global__ void __launch_bounds__(256)
ssd_inter_k(const float* __restrict__ Dp) {
    const int it = blockIdx.x, h = blockIdx.y, c = blockIdx.z;
    const int g = h >> 4;
    const int tid = threadIdx.x;
    const int tx = tid & 15, ty = tid >> 4;

    __shared__ float CsT[64 * 68];
    __shared__ float Pn [64 * 68];

    const int li0 = c * CSz + it * 64;
    const int ccol = INTERC + Gg * Nn + g * Nn;
    const size_t pbase = ((size_t)(c * Hh + h) * Pp) * Nn;

    float acc[4][4];
#pragma unroll
    for (int i = 0; i < 4; ++i)
#pragma unroll
        for (int j = 0; j < 4; ++j) acc[i][j] = 0.f;

#pragma unroll
    for (int nt = 0; nt < 2; ++nt) {
        __syncthreads();
        {
            int bi = (tid & 15) * 4;
            int bn = (tid >> 4) * 4;
            float4 r0 = *(const float4*)(&d_xbc[(size_t)(li0 + bi + 0) * CONVC + ccol + nt * 64 + bn]);
            float4 r1 = *(const float4*)(&d_xbc[(size_t)(li0 + bi + 1) * CONVC + ccol + nt * 64 + bn]);
            float4 r2 = *(const float4*)(&d_xbc[(size_t)(li0 + bi + 2) * CONVC + ccol + nt * 64 + bn]);
            float4 r3 = *(const float4*)(&d_xbc[(size_t)(li0 + bi + 3) * CONVC + ccol + nt * 64 + bn]);
            *(float4*)&CsT[(bn + 0) * 68 + bi] = make_float4(r0.x, r1.x, r2.x, r3.x);
            *(float4*)&CsT[(bn + 1) * 68 + bi] = make_float4(r0.y, r1.y, r2.y, r3.y);
            *(float4*)&CsT[(bn + 2) * 68 + bi] = make_float4(r0.z, r1.z, r2.z, r3.z);
            *(float4*)&CsT[(bn + 3) * 68 + bi] = make_float4(r0.w, r1.w, r2.w, r3.w);
            float4 p0 = *(const float4*)(&d_prev[pbase + (size_t)(bi + 0) * Nn + nt * 64 + bn]);
            float4 p1 = *(const float4*)(&d_prev[pbase + (size_t)(bi + 1) * Nn + nt * 64 + bn]);
            float4 p2 = *(const float4*)(&d_prev[pbase + (size_t)(bi + 2) * Nn + nt * 64 + bn]);
            float4 p3 = *(const float4*)(&d_prev[pbase + (size_t)(bi + 3) * Nn + nt * 64 + bn]);
            *(float4*)&Pn[(bn + 0) * 68 + bi] = make_float4(p0.x, p1.x, p2.x, p3.x);
            *(float4*)&Pn[(bn + 1) * 68 + bi] = make_float4(p0.y, p1.y, p2.y, p3.y);
            *(float4*)&Pn[(bn + 2) * 68 + bi] = make_float4(p0.z, p1.z, p2.z, p3.z);
            *(float4*)&Pn[(bn + 3) * 68 + bi] = make_float4(p0.w, p1.w, p2.w, p3.w);
        }
        __syncthreads();
#pragma unroll 8
        for (int kk = 0; kk < 64; ++kk) {
            float4 a4 = *(const float4*)&CsT[kk * 68 + ty * 4];
            float4 b4 = *(const float4*)&Pn[kk * 68 + tx * 4];
            float a[4] = {a4.x, a4.y, a4.z, a4.w};
            float b[4] = {b4.x, b4.y, b4.z, b4.w};
#pragma unroll
            for (int i = 0; i < 4; ++i)
#pragma unroll
                for (int j = 0; j < 4; ++j) acc[i][j] += a[i] * b[j];
        }
    }
    const float Dh = Dp[h];
#pragma unroll
    for (int i = 0; i < 4; ++i) {
        int l = li0 + ty * 4 + i;
        float esc = __expf(d_cum[(size_t)l * Hh + h]);
        size_t yi = (size_t)l * INTERC + h * Pp + tx * 4;
        size_t xi = (size_t)l * CONVC + h * Pp + tx * 4;
        float4 yv = *(const float4*)&d_y[yi];
        float4 xv = *(const float4*)&d_xbc[xi];
        yv.x += esc * acc[i][0] + Dh * xv.x;
        yv.y += esc * acc[i][1] + Dh * xv.y;
        yv.z += esc * acc[i][2] + Dh * xv.z;
        yv.w += esc * acc[i][3] + Dh * xv.w;
        *(float4*)&d_y[yi] = yv;
    }
}

// ---------------- gated RMS group-norm (writes tf32-rounded d_g) ----------------
__global__ void __launch_bounds__(256)
gated_norm_k(const float* __restrict__ norm_w) {
    const int l = blockIdx.x, grp = blockIdx.y;
    const int tid = threadIdx.x;
    float v[4];
    float ss = 0.f;
#pragma unroll
    for (int i = 0; i < 4; ++i) {
        int col = grp * GSZ + tid + i * 256;
        float gate = d_proj[(size_t)l * PROJC + col];
        float yv = d_y[(size_t)l * INTERC + col];
        float sg = gate / (1.f + __expf(-gate));
        v[i] = yv * sg;
        ss += v[i] * v[i];
    }
#pragma unroll
    for (int off = 16; off; off >>= 1) ss += __shfl_xor_sync(0xffffffffu, ss, off);
    __shared__ float red[8];
    if ((tid & 31) == 0) red[tid >> 5] = ss;
    __syncthreads();
    float tot = red[0] + red[1] + red[2] + red[3] + red[4] + red[5] + red[6] + red[7];
    float rs = rsqrtf(tot / (float)GSZ + EPSf);
#pragma unroll
    for (int i = 0; i < 4; ++i) {
        int col = grp * GSZ + tid + i * 256;
        d_g[(size_t)l * INTERC + col] = __uint_as_float(f2tf32(v[i] * rs * norm_w[col]));
    }
}

// ---------------- launch ----------------
extern "C" void kernel_launch(void* const* d_in, const int* in_sizes, int n_in,
                              void* d_out, int out_size) {
    const float* input     = (const float*)d_in[0];
    const float* in_proj_w = (const float*)d_in[1];
    const float* conv_w    = (const float*)d_in[2];
    const float* conv_b    = (const float*)d_in[3];
    const float* dt_bias   = (const float*)d_in[4];
    const float* A_log     = (const float*)d_in[5];
    const float* Dp        = (const float*)d_in[6];
    const float* norm_w    = (const float*)d_in[7];
    const float* out_w     = (const float*)d_in[8];
    float* out = (float*)d_out;

    cudaFuncSetAttribute(gemm1_mma_k, cudaFuncAttributeMaxDynamicSharedMemorySize, GM_SMEM);
    cudaFuncSetAttribute(gemm2_mma_k, cudaFuncAttributeMaxDynamicSharedMemorySize, GM_SMEM);
    cudaFuncSetAttribute(ssd_intra_k, cudaFuncAttributeMaxDynamicSharedMemorySize, IT_SMEM);

    float* wa;  cudaGetSymbolAddress((void**)&wa,  d_wa);
    float* wb1; cudaGetSymbolAddress((void**)&wb1, d_wb1);
    float* wb2; cudaGetSymbolAddress((void**)&wb2, d_wb2);

    // 0. tf32 pre-converts
    cvt_tf32_k<<<(Lq * HIDm / 4 + 255) / 256, 256>>>((const float4*)input, (float4*)wa, Lq * HIDm / 4);
    cvt_tf32_k<<<((size_t)PROJC * HIDm / 4 + 255) / 256, 256>>>((const float4*)in_proj_w, (float4*)wb1, PROJC * HIDm / 4);
    cvt_tf32_k<<<((size_t)HIDm * INTERC / 4 + 255) / 256, 256>>>((const float4*)out_w, (float4*)wb2, HIDm * INTERC / 4);

    // 1. in_proj GEMM (tf32): (2048x4096) @ (18560x4096)^T -> d_proj
    gemm1_mma_k<<<dim3(Lq / BMt, PROJC / BNt), 256, GM_SMEM>>>();
    // 2. depthwise causal conv + SiLU -> d_xbc
    conv_silu_k<<<dim3(CONVC / 256, Lq), 256>>>(conv_w, conv_b);
    // 3. dt softplus + per-chunk cumsum(dA)
    dt_cum_k<<<dim3(Hh, NC), 256>>>(dt_bias, A_log);
    // 4. intra-chunk pass -> d_y
    ssd_intra_k<<<dim3(4, Hh, NC), 256, IT_SMEM>>>();
    // 5. per-chunk states
    ssd_states_k<<<dim3(Hh, NC), 256>>>();
    // 6. inter-chunk sequential scan -> d_prev
    ssd_scan_k<<<(Hh * Pp * Nn) / 256, 256>>>();
    // 7. inter-chunk contribution + D*x -> d_y (final)
    ssd_inter_k<<<dim3(4, Hh, NC), 256>>>(Dp);
    // 8. gated RMS group-norm -> d_g (tf32-rounded)
    gated_norm_k<<<dim3(Lq, Gg), 256>>>(norm_w);
    // 9. out GEMM (tf32): (2048x8192) @ (4096x8192)^T -> out
    gemm2_mma_k<<<dim3(Lq / BMt, HIDm / BNt), 256, GM_SMEM>>>(out);
}

// round 6
// speedup vs baseline: 1.5485x; 1.5485x over previous
#include <cuda_runtime.h>
#include <cuda_fp16.h>
#include <math.h>
#include <stdint.h>

// ---------------- problem constants ----------------
#define Lq     2048
#define HIDm   4096
#define Hh     128
#define Pp     64
#define Nn     128
#define Gg     8
#define Kk     4
#define CSz    256
#define NC     8            // L / CS
#define INTERC 8192         // H*P
#define CONVC  10240        // INTER + 2*G*N
#define PROJC  18560        // INTER + CONV + H
#define GSZ    1024         // INTER / G
#define EPSf   1e-5f

// ---------------- scratch (static device globals; no allocation) ----------------
__device__ float d_proj[(size_t)Lq * PROJC];
__device__ float d_xbc [(size_t)Lq * CONVC];
__device__ float d_dt  [(size_t)Lq * Hh];
__device__ float d_cum [(size_t)Lq * Hh];
__device__ float d_y   [(size_t)Lq * INTERC];
__device__ float d_st  [(size_t)NC * Hh * Pp * Nn];
__device__ float d_prev[(size_t)NC * Hh * Pp * Nn];
// fp16 GEMM operands
__device__ __align__(16) __half d_ha [(size_t)Lq * HIDm];        //  16 MB
__device__ __align__(16) __half d_hb1[(size_t)PROJC * HIDm];     // 152 MB
__device__ __align__(16) __half d_hb2[(size_t)HIDm * INTERC];    //  67 MB
__device__ __align__(16) __half d_gh [(size_t)Lq * INTERC];      //  33 MB

__device__ __forceinline__ uint32_t smem_u32(const void* p) {
    return (uint32_t)__cvta_generic_to_shared(p);
}
__device__ __forceinline__ void cp16(uint32_t dst, const void* src) {
    asm volatile("cp.async.cg.shared.global [%0], [%1], 16;\n" :: "r"(dst), "l"(src));
}
__device__ __forceinline__ void mma_f16(float* c, const uint32_t* a, const uint32_t* b) {
    asm volatile(
        "mma.sync.aligned.m16n8k16.row.col.f32.f16.f16.f32 "
        "{%0,%1,%2,%3}, {%4,%5,%6,%7}, {%8,%9}, {%0,%1,%2,%3};"
        : "+f"(c[0]), "+f"(c[1]), "+f"(c[2]), "+f"(c[3])
        : "r"(a[0]), "r"(a[1]), "r"(a[2]), "r"(a[3]), "r"(b[0]), "r"(b[1]));
}

// ---------------- fp32 -> fp16 pre-convert (float4 -> 4 halves) ----------------
__global__ void __launch_bounds__(256)
cvt_f16_k(const float4* __restrict__ in, uint2* __restrict__ outp, int n4) {
    int i = blockIdx.x * 256 + threadIdx.x;
    if (i >= n4) return;
    float4 v = in[i];
    __half2 lo = __floats2half2_rn(v.x, v.y);
    __half2 hi = __floats2half2_rn(v.z, v.w);
    uint2 o;
    o.x = *(const uint32_t*)&lo;
    o.y = *(const uint32_t*)&hi;
    outp[i] = o;
}

// =====================================================================
//  fp16 mma.sync GEMM: C[M,Ncols] = A[M,K] @ B[Ncols,K]^T (half in, f32 out)
//  CTA tile 256x128, BK=64 halves, 256 thr, 8 warps (4m x 2n, 64x64),
//  3-stage cp.async ring, one sync per chunk.
// =====================================================================
#define BMt 256
#define BNt 128
#define BKh 64                          // K per chunk (halves)
#define PADh 72                         // halves per smem row (36 words)
#define STAGE_H ((BMt + BNt) * PADh)    // 27648 halves = 55296 B
#define GM_SMEM (3 * STAGE_H * 2)       // 165888 bytes

__device__ __forceinline__ void gemm_f16_body(const __half* __restrict__ A,
                                              const __half* __restrict__ B,
                                              float* __restrict__ C,
                                              int Ncols, int K) {
    extern __shared__ __half smh[];
    const uint32_t sbase = smem_u32(smh);
    const int tid = threadIdx.x, wid = tid >> 5, lane = tid & 31;
    const int g = lane >> 2, q = lane & 3;
    const int m0 = blockIdx.x * BMt;
    const int n0 = blockIdx.y * BNt;
    const int wm = (wid >> 1) * 64;
    const int wn = (wid & 1) * 64;
    const int nk = K / BKh;

    float acc[4][8][4];
#pragma unroll
    for (int i = 0; i < 4; ++i)
#pragma unroll
        for (int j = 0; j < 8; ++j)
#pragma unroll
            for (int r = 0; r < 4; ++r) acc[i][j][r] = 0.f;

    auto load_stage = [&](int c) {
        const int s = c % 3;
        const int k0 = c * BKh;
        const uint32_t abase = sbase + s * STAGE_H * 2;
        const uint32_t bbase = abase + BMt * PADh * 2;
#pragma unroll
        for (int i = 0; i < 8; ++i) {     // A: 256 rows x 8 cp16 (64 halves)
            int t = tid + i * 256;
            int r = t >> 3, qq = t & 7;
            cp16(abase + (uint32_t)(r * PADh + qq * 8) * 2,
                 A + (size_t)(m0 + r) * K + k0 + qq * 8);
        }
#pragma unroll
        for (int i = 0; i < 4; ++i) {     // B: 128 rows x 8 cp16
            int t = tid + i * 256;
            int r = t >> 3, qq = t & 7;
            cp16(bbase + (uint32_t)(r * PADh + qq * 8) * 2,
                 B + (size_t)(n0 + r) * K + k0 + qq * 8);
        }
        asm volatile("cp.async.commit_group;");
    };

    load_stage(0);
    load_stage(1);

    for (int c = 0; c < nk; ++c) {
        if (c + 1 < nk) {
            asm volatile("cp.async.wait_group 1;");
        } else {
            asm volatile("cp.async.wait_group 0;");
        }
        __syncthreads();

        if (c + 2 < nk) load_stage(c + 2);

        const uint32_t* aw = (const uint32_t*)(smh + (c % 3) * STAGE_H);
        const uint32_t* bw = aw + BMt * (PADh / 2);

#pragma unroll
        for (int ks = 0; ks < 4; ++ks) {        // 4 k-steps of 16
            const int kw = ks * 8;              // word offset within row
            uint32_t af[4][4];
#pragma unroll
            for (int mi = 0; mi < 4; ++mi) {
                int base = (wm + mi * 16 + g) * 36 + kw + q;
                af[mi][0] = aw[base];
                af[mi][1] = aw[base + 8 * 36];
                af[mi][2] = aw[base + 4];
                af[mi][3] = aw[base + 8 * 36 + 4];
            }
            uint32_t bf[8][2];
#pragma unroll
            for (int ni = 0; ni < 8; ++ni) {
                int base = (wn + ni * 8 + g) * 36 + kw + q;
                bf[ni][0] = bw[base];
                bf[ni][1] = bw[base + 4];
            }
#pragma unroll
            for (int mi = 0; mi < 4; ++mi)
#pragma unroll
                for (int ni = 0; ni < 8; ++ni)
                    mma_f16(acc[mi][ni], af[mi], bf[ni]);
        }
    }

#pragma unroll
    for (int mi = 0; mi < 4; ++mi) {
        const int r = m0 + wm + mi * 16 + g;
#pragma unroll
        for (int ni = 0; ni < 8; ++ni) {
            const int cb = n0 + wn + ni * 8 + 2 * q;
            *(float2*)(C + (size_t)r * Ncols + cb) =
                make_float2(acc[mi][ni][0], acc[mi][ni][1]);
            *(float2*)(C + (size_t)(r + 8) * Ncols + cb) =
                make_float2(acc[mi][ni][2], acc[mi][ni][3]);
        }
    }
}

__global__ void __launch_bounds__(256, 1)
gemm1_mma_k() { gemm_f16_body(d_ha, d_hb1, d_proj, PROJC, HIDm); }
__global__ void __launch_bounds__(256, 1)
gemm2_mma_k(float* __restrict__ C) { gemm_f16_body(d_gh, d_hb2, C, HIDm, INTERC); }

// ---------------- depthwise causal conv (K=4) + SiLU ----------------
__global__ void __launch_bounds__(256)
conv_silu_k(const float* __restrict__ w, const float* __restrict__ b) {
    int c = blockIdx.x * 256 + threadIdx.x;
    int l = blockIdx.y;
    if (c >= CONVC) return;
    float acc = b[c];
#pragma unroll
    for (int k = 0; k < Kk; ++k) {
        int ls = l - (Kk - 1) + k;
        if (ls >= 0) acc += w[c * Kk + k] * d_proj[(size_t)ls * PROJC + INTERC + c];
    }
    d_xbc[(size_t)l * CONVC + c] = acc / (1.f + __expf(-acc));
}

// ---------------- dt softplus + per-chunk cumsum of dA ----------------
__global__ void __launch_bounds__(256)
dt_cum_k(const float* __restrict__ dt_bias, const float* __restrict__ A_log) {
    int h = blockIdx.x, c = blockIdx.y, t = threadIdx.x;
    int l = c * CSz + t;
    float x = d_proj[(size_t)l * PROJC + (INTERC + CONVC) + h] + dt_bias[h];
    float sp = fmaxf(x, 0.f) + log1pf(expf(-fabsf(x)));
    float dtv = fmaxf(sp, 0.f);
    float A = -expf(A_log[h]);
    __shared__ float s[CSz];
    s[t] = dtv * A;
    __syncthreads();
    for (int off = 1; off < CSz; off <<= 1) {
        float v = (t >= off) ? s[t - off] : 0.f;
        __syncthreads();
        s[t] += v;
        __syncthreads();
    }
    d_dt [(size_t)l * Hh + h] = dtv;
    d_cum[(size_t)l * Hh + h] = s[t];
}

// ---------------- intra-chunk: y_intra = (CB^T * Ldec * dt) @ x ----------------
#define IT_SMEM ((2 * 128 * 68 + 2 * 64 * 68 + 192) * 4)
__global__ void __launch_bounds__(256, 2)
ssd_intra_k() {
    extern __shared__ float sdyn[];
    float* CsT = sdyn;                 // [n][i]  128x68
    float* BsT = CsT + 128 * 68;       // [n][j]  128x68
    float* SsT = BsT + 128 * 68;       // [j][i]   64x68
    float* Xs  = SsT + 64 * 68;        // [j][p]   64x68
    float* cum_i = Xs + 64 * 68;
    float* cum_j = cum_i + 64;
    float* dtj   = cum_j + 64;

    const int it = blockIdx.x, h = blockIdx.y, c = blockIdx.z;
    const int g = h >> 4;
    const int tid = threadIdx.x;
    const int tx = tid & 15, ty = tid >> 4;

    const int li0 = c * CSz + it * 64;
    const int ccol = INTERC + Gg * Nn + g * Nn;
    const int bcol = INTERC + g * Nn;

#pragma unroll
    for (int rep = 0; rep < 2; ++rep) {
        int b = tid + rep * 256;
        int bi = (b & 15) * 4;
        int bn = (b >> 4) * 4;
        float4 r0 = *(const float4*)(&d_xbc[(size_t)(li0 + bi + 0) * CONVC + ccol + bn]);
        float4 r1 = *(const float4*)(&d_xbc[(size_t)(li0 + bi + 1) * CONVC + ccol + bn]);
        float4 r2 = *(const float4*)(&d_xbc[(size_t)(li0 + bi + 2) * CONVC + ccol + bn]);
        float4 r3 = *(const float4*)(&d_xbc[(size_t)(li0 + bi + 3) * CONVC + ccol + bn]);
        *(float4*)&CsT[(bn + 0) * 68 + bi] = make_float4(r0.x, r1.x, r2.x, r3.x);
        *(float4*)&CsT[(bn + 1) * 68 + bi] = make_float4(r0.y, r1.y, r2.y, r3.y);
        *(float4*)&CsT[(bn + 2) * 68 + bi] = make_float4(r0.z, r1.z, r2.z, r3.z);
        *(float4*)&CsT[(bn + 3) * 68 + bi] = make_float4(r0.w, r1.w, r2.w, r3.w);
    }
    if (tid < 64) cum_i[tid] = d_cum[(size_t)(li0 + tid) * Hh + h];

    float yacc[4][4];
#pragma unroll
    for (int i = 0; i < 4; ++i)
#pragma unroll
        for (int j = 0; j < 4; ++j) yacc[i][j] = 0.f;

    for (int jt = 0; jt <= it; ++jt) {
        const int lj0 = c * CSz + jt * 64;
        __syncthreads();
#pragma unroll
        for (int rep = 0; rep < 2; ++rep) {
            int b = tid + rep * 256;
            int bi = (b & 15) * 4;
            int bn = (b >> 4) * 4;
            float4 r0 = *(const float4*)(&d_xbc[(size_t)(lj0 + bi + 0) * CONVC + bcol + bn]);
            float4 r1 = *(const float4*)(&d_xbc[(size_t)(lj0 + bi + 1) * CONVC + bcol + bn]);
            float4 r2 = *(const float4*)(&d_xbc[(size_t)(lj0 + bi + 2) * CONVC + bcol + bn]);
            float4 r3 = *(const float4*)(&d_xbc[(size_t)(lj0 + bi + 3) * CONVC + bcol + bn]);
            *(float4*)&BsT[(bn + 0) * 68 + bi] = make_float4(r0.x, r1.x, r2.x, r3.x);
            *(float4*)&BsT[(bn + 1) * 68 + bi] = make_float4(r0.y, r1.y, r2.y, r3.y);
            *(float4*)&BsT[(bn + 2) * 68 + bi] = make_float4(r0.z, r1.z, r2.z, r3.z);
            *(float4*)&BsT[(bn + 3) * 68 + bi] = make_float4(r0.w, r1.w, r2.w, r3.w);
        }
#pragma unroll
        for (int rep = 0; rep < 4; ++rep) {
            int idx = tid + rep * 256;
            int r = idx >> 4, qq = idx & 15;
            *(float4*)&Xs[r * 68 + qq * 4] =
                *(const float4*)(&d_xbc[(size_t)(lj0 + r) * CONVC + h * Pp + qq * 4]);
        }
        if (tid < 64) {
            cum_j[tid] = d_cum[(size_t)(lj0 + tid) * Hh + h];
            dtj  [tid] = d_dt [(size_t)(lj0 + tid) * Hh + h];
        }
        __syncthreads();

        float sacc[4][4];
#pragma unroll
        for (int i = 0; i < 4; ++i)
#pragma unroll
            for (int j = 0; j < 4; ++j) sacc[i][j] = 0.f;
#pragma unroll 8
        for (int kk = 0; kk < 128; ++kk) {
            float4 a4 = *(const float4*)&CsT[kk * 68 + ty * 4];
            float4 b4 = *(const float4*)&BsT[kk * 68 + tx * 4];
            float a[4] = {a4.x, a4.y, a4.z, a4.w};
            float b[4] = {b4.x, b4.y, b4.z, b4.w};
#pragma unroll
            for (int i = 0; i < 4; ++i)
#pragma unroll
                for (int j = 0; j < 4; ++j) sacc[i][j] += a[i] * b[j];
        }
#pragma unroll
        for (int jj = 0; jj < 4; ++jj) {
            int gj = jt * 64 + tx * 4 + jj;
            float cjv = cum_j[tx * 4 + jj];
            float djv = dtj[tx * 4 + jj];
            float v[4];
#pragma unroll
            for (int ii = 0; ii < 4; ++ii) {
                int gi = it * 64 + ty * 4 + ii;
                v[ii] = (gi >= gj) ? sacc[ii][jj] * __expf(cum_i[ty * 4 + ii] - cjv) * djv : 0.f;
            }
            *(float4*)&SsT[(tx * 4 + jj) * 68 + ty * 4] = make_float4(v[0], v[1], v[2], v[3]);
        }
        __syncthreads();

#pragma unroll 8
        for (int kkj = 0; kkj < 64; ++kkj) {
            float4 a4 = *(const float4*)&SsT[kkj * 68 + ty * 4];
            float4 b4 = *(const float4*)&Xs[kkj * 68 + tx * 4];
            float a[4] = {a4.x, a4.y, a4.z, a4.w};
            float b[4] = {b4.x, b4.y, b4.z, b4.w};
#pragma unroll
            for (int i = 0; i < 4; ++i)
#pragma unroll
                for (int j = 0; j < 4; ++j) yacc[i][j] += a[i] * b[j];
        }
    }
#pragma unroll
    for (int i = 0; i < 4; ++i) {
        *(float4*)(&d_y[(size_t)(li0 + ty * 4 + i) * INTERC + h * Pp + tx * 4]) =
            make_float4(yacc[i][0], yacc[i][1], yacc[i][2], yacc[i][3]);
    }
}

// ---------------- chunk states ----------------
__global__ void __launch_bounds__(256)
ssd_states_k() {
    const int h = blockIdx.x, c = blockIdx.y;
    const int g = h >> 4;
    const int tid = threadIdx.x;
    const int tx = tid & 15, ty = tid >> 4;

    __shared__ float Xs[32][68];
    __shared__ float Bsh[32][132];
    __shared__ float ws[32];

    float acc[4][8];
#pragma unroll
    for (int i = 0; i < 4; ++i)
#pragma unroll
        for (int j = 0; j < 8; ++j) acc[i][j] = 0.f;

    const float cum_last = d_cum[(size_t)(c * CSz + CSz - 1) * Hh + h];

    for (int j0 = 0; j0 < CSz; j0 += 32) {
        __syncthreads();
#pragma unroll
        for (int rep = 0; rep < 2; ++rep) {
            int idx = tid + rep * 256;
            int r = idx >> 4, q = idx & 15;
            *(float4*)&Xs[r][q * 4] =
                *(const float4*)(&d_xbc[(size_t)(c * CSz + j0 + r) * CONVC + h * Pp + q * 4]);
        }
#pragma unroll
        for (int rep = 0; rep < 4; ++rep) {
            int idx = tid + rep * 256;
            int r = idx >> 5, q = idx & 31;
            *(float4*)&Bsh[r][q * 4] =
                *(const float4*)(&d_xbc[(size_t)(c * CSz + j0 + r) * CONVC + INTERC + g * Nn + q * 4]);
        }
        if (tid < 32) {
            int l = c * CSz + j0 + tid;
            ws[tid] = d_dt[(size_t)l * Hh + h] * __expf(cum_last - d_cum[(size_t)l * Hh + h]);
        }
        __syncthreads();
#pragma unroll 4
        for (int j = 0; j < 32; ++j) {
            float w = ws[j];
            float4 a4 = *(const float4*)&Xs[j][ty * 4];
            float aw[4] = {a4.x * w, a4.y * w, a4.z * w, a4.w * w};
            float4 b0 = *(const float4*)&Bsh[j][tx * 8];
            float4 b1 = *(const float4*)&Bsh[j][tx * 8 + 4];
            float b[8] = {b0.x, b0.y, b0.z, b0.w, b1.x, b1.y, b1.z, b1.w};
#pragma unroll
            for (int i = 0; i < 4; ++i)
#pragma unroll
                for (int jn = 0; jn < 8; ++jn) acc[i][jn] += aw[i] * b[jn];
        }
    }
#pragma unroll
    for (int i = 0; i < 4; ++i) {
        size_t base = ((size_t)(c * Hh + h) * Pp + ty * 4 + i) * Nn + tx * 8;
        *(float4*)&d_st[base]     = make_float4(acc[i][0], acc[i][1], acc[i][2], acc[i][3]);
        *(float4*)&d_st[base + 4] = make_float4(acc[i][4], acc[i][5], acc[i][6], acc[i][7]);
    }
}

// ---------------- inter-chunk scan ----------------
__global__ void __launch_bounds__(256)
ssd_scan_k() {
    int idx = blockIdx.x * 256 + threadIdx.x;
    if (idx >= Hh * Pp * Nn) return;
    int h = idx / (Pp * Nn);
    float carry = 0.f;
#pragma unroll
    for (int c = 0; c < NC; ++c) {
        d_prev[(size_t)c * Hh * Pp * Nn + idx] = carry;
        float cdec = __expf(d_cum[(size_t)(c * CSz + CSz - 1) * Hh + h]);
        carry = cdec * carry + d_st[(size_t)c * Hh * Pp * Nn + idx];
    }
}

// ---------------- inter-chunk output + D*x ----------------
__global__ void __launch_bounds__(256)
ssd_inter_k(const float* __restrict__ Dp) {
    const int it = blockIdx.x, h = blockIdx.y, c = blockIdx.z;
    const int g = h >> 4;
    const int tid = threadIdx.x;
    const int tx = tid & 15, ty = tid >> 4;

    __shared__ float CsT[64 * 68];
    __shared__ float Pn [64 * 68];

    const int li0 = c * CSz + it * 64;
    const int ccol = INTERC + Gg * Nn + g * Nn;
    const size_t pbase = ((size_t)(c * Hh + h) * Pp) * Nn;

    float acc[4][4];
#pragma unroll
    for (int i = 0; i < 4; ++i)
#pragma unroll
        for (int j = 0; j < 4; ++j) acc[i][j] = 0.f;

#pragma unroll
    for (int nt = 0; nt < 2; ++nt) {
        __syncthreads();
        {
            int bi = (tid & 15) * 4;
            int bn = (tid >> 4) * 4;
            float4 r0 = *(const float4*)(&d_xbc[(size_t)(li0 + bi + 0) * CONVC + ccol + nt * 64 + bn]);
            float4 r1 = *(const float4*)(&d_xbc[(size_t)(li0 + bi + 1) * CONVC + ccol + nt * 64 + bn]);
            float4 r2 = *(const float4*)(&d_xbc[(size_t)(li0 + bi + 2) * CONVC + ccol + nt * 64 + bn]);
            float4 r3 = *(const float4*)(&d_xbc[(size_t)(li0 + bi + 3) * CONVC + ccol + nt * 64 + bn]);
            *(float4*)&CsT[(bn + 0) * 68 + bi] = make_float4(r0.x, r1.x, r2.x, r3.x);
            *(float4*)&CsT[(bn + 1) * 68 + bi] = make_float4(r0.y, r1.y, r2.y, r3.y);
            *(float4*)&CsT[(bn + 2) * 68 + bi] = make_float4(r0.z, r1.z, r2.z, r3.z);
            *(float4*)&CsT[(bn + 3) * 68 + bi] = make_float4(r0.w, r1.w, r2.w, r3.w);
            float4 p0 = *(const float4*)(&d_prev[pbase + (size_t)(bi + 0) * Nn + nt * 64 + bn]);
            float4 p1 = *(const float4*)(&d_prev[pbase + (size_t)(bi + 1) * Nn + nt * 64 + bn]);
            float4 p2 = *(const float4*)(&d_prev[pbase + (size_t)(bi + 2) * Nn + nt * 64 + bn]);
            float4 p3 = *(const float4*)(&d_prev[pbase + (size_t)(bi + 3) * Nn + nt * 64 + bn]);
            *(float4*)&Pn[(bn + 0) * 68 + bi] = make_float4(p0.x, p1.x, p2.x, p3.x);
            *(float4*)&Pn[(bn + 1) * 68 + bi] = make_float4(p0.y, p1.y, p2.y, p3.y);
            *(float4*)&Pn[(bn + 2) * 68 + bi] = make_float4(p0.z, p1.z, p2.z, p3.z);
            *(float4*)&Pn[(bn + 3) * 68 + bi] = make_float4(p0.w, p1.w, p2.w, p3.w);
        }
        __syncthreads();
#pragma unroll 8
        for (int kk = 0; kk < 64; ++kk) {
            float4 a4 = *(const float4*)&CsT[kk * 68 + ty * 4];
            float4 b4 = *(const float4*)&Pn[kk * 68 + tx * 4];
            float a[4] = {a4.x, a4.y, a4.z, a4.w};
            float b[4] = {b4.x, b4.y, b4.z, b4.w};
#pragma unroll
            for (int i = 0; i < 4; ++i)
#pragma unroll
                for (int j = 0; j < 4; ++j) acc[i][j] += a[i] * b[j];
        }
    }
    const float Dh = Dp[h];
#pragma unroll
    for (int i = 0; i < 4; ++i) {
        int l = li0 + ty * 4 + i;
        float esc = __expf(d_cum[(size_t)l * Hh + h]);
        size_t yi = (size_t)l * INTERC + h * Pp + tx * 4;
        size_t xi = (size_t)l * CONVC + h * Pp + tx * 4;
        float4 yv = *(const float4*)&d_y[yi];
        float4 xv = *(const float4*)&d_xbc[xi];
        yv.x += esc * acc[i][0] + Dh * xv.x;
        yv.y += esc * acc[i][1] + Dh * xv.y;
        yv.z += esc * acc[i][2] + Dh * xv.z;
        yv.w += esc * acc[i][3] + Dh * xv.w;
        *(float4*)&d_y[yi] = yv;
    }
}

// ---------------- gated RMS group-norm (writes fp16 d_gh) ----------------
__global__ void __launch_bounds__(256)
gated_norm_k(const float* __restrict__ norm_w) {
    const int l = blockIdx.x, grp = blockIdx.y;
    const int tid = threadIdx.x;
    float v[4];
    float ss = 0.f;
#pragma unroll
    for (int i = 0; i < 4; ++i) {
        int col = grp * GSZ + tid + i * 256;
        float gate = d_proj[(size_t)l * PROJC + col];
        float yv = d_y[(size_t)l * INTERC + col];
        float sg = gate / (1.f + __expf(-gate));
        v[i] = yv * sg;
        ss += v[i] * v[i];
    }
#pragma unroll
    for (int off = 16; off; off >>= 1) ss += __shfl_xor_sync(0xffffffffu, ss, off);
    __shared__ float red[8];
    if ((tid & 31) == 0) red[tid >> 5] = ss;
    __syncthreads();
    float tot = red[0] + red[1] + red[2] + red[3] + red[4] + red[5] + red[6] + red[7];
    float rs = rsqrtf(tot / (float)GSZ + EPSf);
#pragma unroll
    for (int i = 0; i < 4; ++i) {
        int col = grp * GSZ + tid + i * 256;
        d_gh[(size_t)l * INTERC + col] = __float2half_rn(v[i] * rs * norm_w[col]);
    }
}

// ---------------- launch ----------------
extern "C" void kernel_launch(void* const* d_in, const int* in_sizes, int n_in,
                              void* d_out, int out_size) {
    const float* input     = (const float*)d_in[0];
    const float* in_proj_w = (const float*)d_in[1];
    const float* conv_w    = (const float*)d_in[2];
    const float* conv_b    = (const float*)d_in[3];
    const float* dt_bias   = (const float*)d_in[4];
    const float* A_log     = (const float*)d_in[5];
    const float* Dp        = (const float*)d_in[6];
    const float* norm_w    = (const float*)d_in[7];
    const float* out_w     = (const float*)d_in[8];
    float* out = (float*)d_out;

    cudaFuncSetAttribute(gemm1_mma_k, cudaFuncAttributeMaxDynamicSharedMemorySize, GM_SMEM);
    cudaFuncSetAttribute(gemm2_mma_k, cudaFuncAttributeMaxDynamicSharedMemorySize, GM_SMEM);
    cudaFuncSetAttribute(ssd_intra_k, cudaFuncAttributeMaxDynamicSharedMemorySize, IT_SMEM);

    __half* ha;  cudaGetSymbolAddress((void**)&ha,  d_ha);
    __half* hb1; cudaGetSymbolAddress((void**)&hb1, d_hb1);
    __half* hb2; cudaGetSymbolAddress((void**)&hb2, d_hb2);

    // 0. fp16 pre-converts
    cvt_f16_k<<<(Lq * HIDm / 4 + 255) / 256, 256>>>((const float4*)input, (uint2*)ha, Lq * HIDm / 4);
    cvt_f16_k<<<(PROJC * HIDm / 4 + 255) / 256, 256>>>((const float4*)in_proj_w, (uint2*)hb1, PROJC * HIDm / 4);
    cvt_f16_k<<<(HIDm * INTERC / 4 + 255) / 256, 256>>>((const float4*)out_w, (uint2*)hb2, HIDm * INTERC / 4);

    // 1. in_proj GEMM (fp16 mma): (2048x4096) @ (18560x4096)^T -> d_proj
    gemm1_mma_k<<<dim3(Lq / BMt, PROJC / BNt), 256, GM_SMEM>>>();
    // 2. depthwise causal conv + SiLU -> d_xbc
    conv_silu_k<<<dim3(CONVC / 256, Lq), 256>>>(conv_w, conv_b);
    // 3. dt softplus + per-chunk cumsum(dA)
    dt_cum_k<<<dim3(Hh, NC), 256>>>(dt_bias, A_log);
    // 4. intra-chunk pass -> d_y
    ssd_intra_k<<<dim3(4, Hh, NC), 256, IT_SMEM>>>();
    // 5. per-chunk states
    ssd_states_k<<<dim3(Hh, NC), 256>>>();
    // 6. inter-chunk sequential scan -> d_prev
    ssd_scan_k<<<(Hh * Pp * Nn) / 256, 256>>>();
    // 7. inter-chunk contribution + D*x -> d_y (final)
    ssd_inter_k<<<dim3(4, Hh, NC), 256>>>(Dp);
    // 8. gated RMS group-norm -> d_gh (fp16)
    gated_norm_k<<<dim3(Lq, Gg), 256>>>(norm_w);
    // 9. out GEMM (fp16 mma): (2048x8192) @ (4096x8192)^T -> out
    gemm2_mma_k<<<dim3(Lq / BMt, HIDm / BNt), 256, GM_SMEM>>>(out);
}

// round 7
// speedup vs baseline: 1.6520x; 1.0668x over previous
#include <cuda_runtime.h>
#include <cuda_fp16.h>
#include <math.h>
#include <stdint.h>

// ---------------- problem constants ----------------
#define Lq     2048
#define HIDm   4096
#define Hh     128
#define Pp     64
#define Nn     128
#define Gg     8
#define Kk     4
#define CSz    256
#define NC     8            // L / CS
#define INTERC 8192         // H*P
#define CONVC  10240        // INTER + 2*G*N
#define PROJC  18560        // INTER + CONV + H
#define GSZ    1024         // INTER / G
#define EPSf   1e-5f

// ---------------- scratch (static device globals; no allocation) ----------------
__device__ float d_proj[(size_t)Lq * PROJC];
__device__ float d_xbc [(size_t)Lq * CONVC];
__device__ float d_dt  [(size_t)Lq * Hh];
__device__ float d_cum [(size_t)Lq * Hh];
__device__ float d_y   [(size_t)Lq * INTERC];
__device__ float d_st  [(size_t)NC * Hh * Pp * Nn];
__device__ float d_prev[(size_t)NC * Hh * Pp * Nn];
// fp16 GEMM operands
__device__ __align__(16) __half d_ha [(size_t)Lq * HIDm];
__device__ __align__(16) __half d_hb1[(size_t)PROJC * HIDm];
__device__ __align__(16) __half d_hb2[(size_t)HIDm * INTERC];
__device__ __align__(16) __half d_gh [(size_t)Lq * INTERC];

__device__ __forceinline__ uint32_t smem_u32(const void* p) {
    return (uint32_t)__cvta_generic_to_shared(p);
}
__device__ __forceinline__ void cp16(uint32_t dst, const void* src) {
    asm volatile("cp.async.cg.shared.global [%0], [%1], 16;\n" :: "r"(dst), "l"(src));
}
__device__ __forceinline__ void mma_f16(float* c, const uint32_t* a, const uint32_t* b) {
    asm volatile(
        "mma.sync.aligned.m16n8k16.row.col.f32.f16.f16.f32 "
        "{%0,%1,%2,%3}, {%4,%5,%6,%7}, {%8,%9}, {%0,%1,%2,%3};"
        : "+f"(c[0]), "+f"(c[1]), "+f"(c[2]), "+f"(c[3])
        : "r"(a[0]), "r"(a[1]), "r"(a[2]), "r"(a[3]), "r"(b[0]), "r"(b[1]));
}
__device__ __forceinline__ void ldm_x4(uint32_t* r, uint32_t addr) {
    asm volatile("ldmatrix.sync.aligned.m8n8.x4.shared.b16 {%0,%1,%2,%3}, [%4];"
                 : "=r"(r[0]), "=r"(r[1]), "=r"(r[2]), "=r"(r[3]) : "r"(addr));
}

// ---------------- fp32 -> fp16 pre-convert ----------------
__global__ void __launch_bounds__(256)
cvt_f16_k(const float4* __restrict__ in, uint2* __restrict__ outp, int n4) {
    int i = blockIdx.x * 256 + threadIdx.x;
    if (i >= n4) return;
    float4 v = in[i];
    __half2 lo = __floats2half2_rn(v.x, v.y);
    __half2 hi = __floats2half2_rn(v.z, v.w);
    uint2 o;
    o.x = *(const uint32_t*)&lo;
    o.y = *(const uint32_t*)&hi;
    outp[i] = o;
}

// =====================================================================
//  fp16 mma GEMM: C[M,Ncols] = A[M,K] @ B[Ncols,K]^T (half in, f32 out)
//  CTA tile 128x128, BK=64, 256 thr, 8 warps (4m x 2n, 32x64 each),
//  3-stage ring, ldmatrix fragment loads, 2 CTAs/SM.
// =====================================================================
#define BMt 128
#define BNt 128
#define BKh 64                          // K per chunk (halves)
#define PADh 72                         // halves per smem row (144 B)
#define STAGE_H ((BMt + BNt) * PADh)    // 18432 halves = 36864 B
#define GM_SMEM (3 * STAGE_H * 2)       // 110592 bytes

__device__ __forceinline__ void gemm_f16_body(const __half* __restrict__ A,
                                              const __half* __restrict__ B,
                                              float* __restrict__ C,
                                              int Ncols, int K) {
    extern __shared__ __half smh[];
    const uint32_t sbase = smem_u32(smh);
    const int tid = threadIdx.x, wid = tid >> 5, lane = tid & 31;
    const int g = lane >> 2, q = lane & 3;
    const int m0 = blockIdx.x * BMt;
    const int n0 = blockIdx.y * BNt;
    const int wm = (wid >> 1) * 32;          // 4 m-warps x 32 rows
    const int wn = (wid & 1) * 64;           // 2 n-warps x 64 cols
    const int nk = K / BKh;

    // ldmatrix per-thread address offsets (bytes within stage)
    const int a_row = wm + (lane & 15);
    const int a_kh  = ((lane >> 4) & 1) * 8;                 // k-half offset
    const uint32_t a_off = (uint32_t)(a_row * PADh + a_kh) * 2;
    const int b_nrow = (lane & 7) + ((lane >> 4) & 1) * 8;   // row within n16
    const int b_kh   = ((lane >> 3) & 1) * 8;
    const uint32_t b_off = (uint32_t)(BMt * PADh + (wn + b_nrow) * PADh + b_kh) * 2;

    float acc[2][8][4];
#pragma unroll
    for (int i = 0; i < 2; ++i)
#pragma unroll
        for (int j = 0; j < 8; ++j)
#pragma unroll
            for (int r = 0; r < 4; ++r) acc[i][j][r] = 0.f;

    auto load_stage = [&](int c) {
        const int s = c % 3;
        const int k0 = c * BKh;
        const uint32_t abase = sbase + s * STAGE_H * 2;
        const uint32_t bbase = abase + BMt * PADh * 2;
#pragma unroll
        for (int i = 0; i < 4; ++i) {        // A: 128 rows x 8 cp16
            int t = tid + i * 256;
            int r = t >> 3, qq = t & 7;
            cp16(abase + (uint32_t)(r * PADh + qq * 8) * 2,
                 A + (size_t)(m0 + r) * K + k0 + qq * 8);
        }
#pragma unroll
        for (int i = 0; i < 4; ++i) {        // B: 128 rows x 8 cp16
            int t = tid + i * 256;
            int r = t >> 3, qq = t & 7;
            cp16(bbase + (uint32_t)(r * PADh + qq * 8) * 2,
                 B + (size_t)(n0 + r) * K + k0 + qq * 8);
        }
        asm volatile("cp.async.commit_group;");
    };

    load_stage(0);
    load_stage(1);

    for (int c = 0; c < nk; ++c) {
        if (c + 1 < nk) {
            asm volatile("cp.async.wait_group 1;");
        } else {
            asm volatile("cp.async.wait_group 0;");
        }
        __syncthreads();

        if (c + 2 < nk) load_stage(c + 2);

        const uint32_t stg = sbase + (uint32_t)(c % 3) * STAGE_H * 2;
        const uint32_t a_addr = stg + a_off;
        const uint32_t b_addr = stg + b_off;

#pragma unroll
        for (int ks = 0; ks < 4; ++ks) {     // 4 k-steps of 16
            const uint32_t kadd = (uint32_t)ks * 32;   // 16 halves
            uint32_t af[2][4];
            ldm_x4(af[0], a_addr + kadd);
            ldm_x4(af[1], a_addr + 16 * PADh * 2 + kadd);
            uint32_t bf[4][4];
#pragma unroll
            for (int nb = 0; nb < 4; ++nb)
                ldm_x4(bf[nb], b_addr + (uint32_t)(nb * 16 * PADh) * 2 + kadd);
#pragma unroll
            for (int mi = 0; mi < 2; ++mi)
#pragma unroll
                for (int ni = 0; ni < 8; ++ni)
                    mma_f16(acc[mi][ni], af[mi], &bf[ni >> 1][(ni & 1) * 2]);
        }
    }

#pragma unroll
    for (int mi = 0; mi < 2; ++mi) {
        const int r = m0 + wm + mi * 16 + g;
#pragma unroll
        for (int ni = 0; ni < 8; ++ni) {
            const int cb = n0 + wn + ni * 8 + 2 * q;
            *(float2*)(C + (size_t)r * Ncols + cb) =
                make_float2(acc[mi][ni][0], acc[mi][ni][1]);
            *(float2*)(C + (size_t)(r + 8) * Ncols + cb) =
                make_float2(acc[mi][ni][2], acc[mi][ni][3]);
        }
    }
}

__global__ void __launch_bounds__(256, 2)
gemm1_mma_k() { gemm_f16_body(d_ha, d_hb1, d_proj, PROJC, HIDm); }
__global__ void __launch_bounds__(256, 2)
gemm2_mma_k(float* __restrict__ C) { gemm_f16_body(d_gh, d_hb2, C, HIDm, INTERC); }

// ---------------- depthwise causal conv (K=4) + SiLU ----------------
__global__ void __launch_bounds__(256)
conv_silu_k(const float* __restrict__ w, const float* __restrict__ b) {
    int c = blockIdx.x * 256 + threadIdx.x;
    int l = blockIdx.y;
    if (c >= CONVC) return;
    float acc = b[c];
#pragma unroll
    for (int k = 0; k < Kk; ++k) {
        int ls = l - (Kk - 1) + k;
        if (ls >= 0) acc += w[c * Kk + k] * d_proj[(size_t)ls * PROJC + INTERC + c];
    }
    d_xbc[(size_t)l * CONVC + c] = acc / (1.f + __expf(-acc));
}

// ---------------- dt softplus + per-chunk cumsum of dA ----------------
__global__ void __launch_bounds__(256)
dt_cum_k(const float* __restrict__ dt_bias, const float* __restrict__ A_log) {
    int h = blockIdx.x, c = blockIdx.y, t = threadIdx.x;
    int l = c * CSz + t;
    float x = d_proj[(size_t)l * PROJC + (INTERC + CONVC) + h] + dt_bias[h];
    float sp = fmaxf(x, 0.f) + log1pf(expf(-fabsf(x)));
    float dtv = fmaxf(sp, 0.f);
    float A = -expf(A_log[h]);
    __shared__ float s[CSz];
    s[t] = dtv * A;
    __syncthreads();
    for (int off = 1; off < CSz; off <<= 1) {
        float v = (t >= off) ? s[t - off] : 0.f;
        __syncthreads();
        s[t] += v;
        __syncthreads();
    }
    d_dt [(size_t)l * Hh + h] = dtv;
    d_cum[(size_t)l * Hh + h] = s[t];
}

// ---------------- intra-chunk: y_intra = (CB^T * Ldec * dt) @ x ----------------
#define IT_SMEM ((2 * 128 * 68 + 2 * 64 * 68 + 192) * 4)
__global__ void __launch_bounds__(256, 2)
ssd_intra_k() {
    extern __shared__ float sdyn[];
    float* CsT = sdyn;                 // [n][i]  128x68
    float* BsT = CsT + 128 * 68;       // [n][j]  128x68
    float* SsT = BsT + 128 * 68;       // [j][i]   64x68
    float* Xs  = SsT + 64 * 68;        // [j][p]   64x68
    float* cum_i = Xs + 64 * 68;
    float* cum_j = cum_i + 64;
    float* dtj   = cum_j + 64;

    const int it = blockIdx.x, h = blockIdx.y, c = blockIdx.z;
    const int g = h >> 4;
    const int tid = threadIdx.x;
    const int tx = tid & 15, ty = tid >> 4;

    const int li0 = c * CSz + it * 64;
    const int ccol = INTERC + Gg * Nn + g * Nn;
    const int bcol = INTERC + g * Nn;

#pragma unroll
    for (int rep = 0; rep < 2; ++rep) {
        int b = tid + rep * 256;
        int bi = (b & 15) * 4;
        int bn = (b >> 4) * 4;
        float4 r0 = *(const float4*)(&d_xbc[(size_t)(li0 + bi + 0) * CONVC + ccol + bn]);
        float4 r1 = *(const float4*)(&d_xbc[(size_t)(li0 + bi + 1) * CONVC + ccol + bn]);
        float4 r2 = *(const float4*)(&d_xbc[(size_t)(li0 + bi + 2) * CONVC + ccol + bn]);
        float4 r3 = *(const float4*)(&d_xbc[(size_t)(li0 + bi + 3) * CONVC + ccol + bn]);
        *(float4*)&CsT[(bn + 0) * 68 + bi] = make_float4(r0.x, r1.x, r2.x, r3.x);
        *(float4*)&CsT[(bn + 1) * 68 + bi] = make_float4(r0.y, r1.y, r2.y, r3.y);
        *(float4*)&CsT[(bn + 2) * 68 + bi] = make_float4(r0.z, r1.z, r2.z, r3.z);
        *(float4*)&CsT[(bn + 3) * 68 + bi] = make_float4(r0.w, r1.w, r2.w, r3.w);
    }
    if (tid < 64) cum_i[tid] = d_cum[(size_t)(li0 + tid) * Hh + h];

    float yacc[4][4];
#pragma unroll
    for (int i = 0; i < 4; ++i)
#pragma unroll
        for (int j = 0; j < 4; ++j) yacc[i][j] = 0.f;

    for (int jt = 0; jt <= it; ++jt) {
        const int lj0 = c * CSz + jt * 64;
        __syncthreads();
#pragma unroll
        for (int rep = 0; rep < 2; ++rep) {
            int b = tid + rep * 256;
            int bi = (b & 15) * 4;
            int bn = (b >> 4) * 4;
            float4 r0 = *(const float4*)(&d_xbc[(size_t)(lj0 + bi + 0) * CONVC + bcol + bn]);
            float4 r1 = *(const float4*)(&d_xbc[(size_t)(lj0 + bi + 1) * CONVC + bcol + bn]);
            float4 r2 = *(const float4*)(&d_xbc[(size_t)(lj0 + bi + 2) * CONVC + bcol + bn]);
            float4 r3 = *(const float4*)(&d_xbc[(size_t)(lj0 + bi + 3) * CONVC + bcol + bn]);
            *(float4*)&BsT[(bn + 0) * 68 + bi] = make_float4(r0.x, r1.x, r2.x, r3.x);
            *(float4*)&BsT[(bn + 1) * 68 + bi] = make_float4(r0.y, r1.y, r2.y, r3.y);
            *(float4*)&BsT[(bn + 2) * 68 + bi] = make_float4(r0.z, r1.z, r2.z, r3.z);
            *(float4*)&BsT[(bn + 3) * 68 + bi] = make_float4(r0.w, r1.w, r2.w, r3.w);
        }
#pragma unroll
        for (int rep = 0; rep < 4; ++rep) {
            int idx = tid + rep * 256;
            int r = idx >> 4, qq = idx & 15;
            *(float4*)&Xs[r * 68 + qq * 4] =
                *(const float4*)(&d_xbc[(size_t)(lj0 + r) * CONVC + h * Pp + qq * 4]);
        }
        if (tid < 64) {
            cum_j[tid] = d_cum[(size_t)(lj0 + tid) * Hh + h];
            dtj  [tid] = d_dt [(size_t)(lj0 + tid) * Hh + h];
        }
        __syncthreads();

        float sacc[4][4];
#pragma unroll
        for (int i = 0; i < 4; ++i)
#pragma unroll
            for (int j = 0; j < 4; ++j) sacc[i][j] = 0.f;
#pragma unroll 8
        for (int kk = 0; kk < 128; ++kk) {
            float4 a4 = *(const float4*)&CsT[kk * 68 + ty * 4];
            float4 b4 = *(const float4*)&BsT[kk * 68 + tx * 4];
            float a[4] = {a4.x, a4.y, a4.z, a4.w};
            float b[4] = {b4.x, b4.y, b4.z, b4.w};
#pragma unroll
            for (int i = 0; i < 4; ++i)
#pragma unroll
                for (int j = 0; j < 4; ++j) sacc[i][j] += a[i] * b[j];
        }
#pragma unroll
        for (int jj = 0; jj < 4; ++jj) {
            int gj = jt * 64 + tx * 4 + jj;
            float cjv = cum_j[tx * 4 + jj];
            float djv = dtj[tx * 4 + jj];
            float v[4];
#pragma unroll
            for (int ii = 0; ii < 4; ++ii) {
                int gi = it * 64 + ty * 4 + ii;
                v[ii] = (gi >= gj) ? sacc[ii][jj] * __expf(cum_i[ty * 4 + ii] - cjv) * djv : 0.f;
            }
            *(float4*)&SsT[(tx * 4 + jj) * 68 + ty * 4] = make_float4(v[0], v[1], v[2], v[3]);
        }
        __syncthreads();

#pragma unroll 8
        for (int kkj = 0; kkj < 64; ++kkj) {
            float4 a4 = *(const float4*)&SsT[kkj * 68 + ty * 4];
            float4 b4 = *(const float4*)&Xs[kkj * 68 + tx * 4];
            float a[4] = {a4.x, a4.y, a4.z, a4.w};
            float b[4] = {b4.x, b4.y, b4.z, b4.w};
#pragma unroll
            for (int i = 0; i < 4; ++i)
#pragma unroll
                for (int j = 0; j < 4; ++j) yacc[i][j] += a[i] * b[j];
        }
    }
#pragma unroll
    for (int i = 0; i < 4; ++i) {
        *(float4*)(&d_y[(size_t)(li0 + ty * 4 + i) * INTERC + h * Pp + tx * 4]) =
            make_float4(yacc[i][0], yacc[i][1], yacc[i][2], yacc[i][3]);
    }
}

// ---------------- chunk states ----------------
__global__ void __launch_bounds__(256)
ssd_states_k() {
    const int h = blockIdx.x, c = blockIdx.y;
    const int g = h >> 4;
    const int tid = threadIdx.x;
    const int tx = tid & 15, ty = tid >> 4;

    __shared__ float Xs[32][68];
    __shared__ float Bsh[32][132];
    __shared__ float ws[32];

    float acc[4][8];
#pragma unroll
    for (int i = 0; i < 4; ++i)
#pragma unroll
        for (int j = 0; j < 8; ++j) acc[i][j] = 0.f;

    const float cum_last = d_cum[(size_t)(c * CSz + CSz - 1) * Hh + h];

    for (int j0 = 0; j0 < CSz; j0 += 32) {
        __syncthreads();
#pragma unroll
        for (int rep = 0; rep < 2; ++rep) {
            int idx = tid + rep * 256;
            int r = idx >> 4, q = idx & 15;
            *(float4*)&Xs[r][q * 4] =
                *(const float4*)(&d_xbc[(size_t)(c * CSz + j0 + r) * CONVC + h * Pp + q * 4]);
        }
#pragma unroll
        for (int rep = 0; rep < 4; ++rep) {
            int idx = tid + rep * 256;
            int r = idx >> 5, q = idx & 31;
            *(float4*)&Bsh[r][q * 4] =
                *(const float4*)(&d_xbc[(size_t)(c * CSz + j0 + r) * CONVC + INTERC + g * Nn + q * 4]);
        }
        if (tid < 32) {
            int l = c * CSz + j0 + tid;
            ws[tid] = d_dt[(size_t)l * Hh + h] * __expf(cum_last - d_cum[(size_t)l * Hh + h]);
        }
        __syncthreads();
#pragma unroll 4
        for (int j = 0; j < 32; ++j) {
            float w = ws[j];
            float4 a4 = *(const float4*)&Xs[j][ty * 4];
            float aw[4] = {a4.x * w, a4.y * w, a4.z * w, a4.w * w};
            float4 b0 = *(const float4*)&Bsh[j][tx * 8];
            float4 b1 = *(const float4*)&Bsh[j][tx * 8 + 4];
            float b[8] = {b0.x, b0.y, b0.z, b0.w, b1.x, b1.y, b1.z, b1.w};
#pragma unroll
            for (int i = 0; i < 4; ++i)
#pragma unroll
                for (int jn = 0; jn < 8; ++jn) acc[i][jn] += aw[i] * b[jn];
        }
    }
#pragma unroll
    for (int i = 0; i < 4; ++i) {
        size_t base = ((size_t)(c * Hh + h) * Pp + ty * 4 + i) * Nn + tx * 8;
        *(float4*)&d_st[base]     = make_float4(acc[i][0], acc[i][1], acc[i][2], acc[i][3]);
        *(float4*)&d_st[base + 4] = make_float4(acc[i][4], acc[i][5], acc[i][6], acc[i][7]);
    }
}

// ---------------- inter-chunk scan ----------------
__global__ void __launch_bounds__(256)
ssd_scan_k() {
    int idx = blockIdx.x * 256 + threadIdx.x;
    if (idx >= Hh * Pp * Nn) return;
    int h = idx / (Pp * Nn);
    float carry = 0.f;
#pragma unroll
    for (int c = 0; c < NC; ++c) {
        d_prev[(size_t)c * Hh * Pp * Nn + idx] = carry;
        float cdec = __expf(d_cum[(size_t)(c * CSz + CSz - 1) * Hh + h]);
        carry = cdec * carry + d_st[(size_t)c * Hh * Pp * Nn + idx];
    }
}

// ---------------- inter-chunk output + D*x ----------------
__global__ void __launch_bounds__(256)
ssd_inter_k(const float* __restrict__ Dp) {
    const int it = blockIdx.x, h = blockIdx.y, c = blockIdx.z;
    const int g = h >> 4;
    const int tid = threadIdx.x;
    const int tx = tid & 15, ty = tid >> 4;

    __shared__ float CsT[64 * 68];
    __shared__ float Pn [64 * 68];

    const int li0 = c * CSz + it * 64;
    const int ccol = INTERC + Gg * Nn + g * Nn;
    const size_t pbase = ((size_t)(c * Hh + h) * Pp) * Nn;

    float acc[4][4];
#pragma unroll
    for (int i = 0; i < 4; ++i)
#pragma unroll
        for (int j = 0; j < 4; ++j) acc[i][j] = 0.f;

#pragma unroll
    for (int nt = 0; nt < 2; ++nt) {
        __syncthreads();
        {
            int bi = (tid & 15) * 4;
            int bn = (tid >> 4) * 4;
            float4 r0 = *(const float4*)(&d_xbc[(size_t)(li0 + bi + 0) * CONVC + ccol + nt * 64 + bn]);
            float4 r1 = *(const float4*)(&d_xbc[(size_t)(li0 + bi + 1) * CONVC + ccol + nt * 64 + bn]);
            float4 r2 = *(const float4*)(&d_xbc[(size_t)(li0 + bi + 2) * CONVC + ccol + nt * 64 + bn]);
            float4 r3 = *(const float4*)(&d_xbc[(size_t)(li0 + bi + 3) * CONVC + ccol + nt * 64 + bn]);
            *(float4*)&CsT[(bn + 0) * 68 + bi] = make_float4(r0.x, r1.x, r2.x, r3.x);
            *(float4*)&CsT[(bn + 1) * 68 + bi] = make_float4(r0.y, r1.y, r2.y, r3.y);
            *(float4*)&CsT[(bn + 2) * 68 + bi] = make_float4(r0.z, r1.z, r2.z, r3.z);
            *(float4*)&CsT[(bn + 3) * 68 + bi] = make_float4(r0.w, r1.w, r2.w, r3.w);
            float4 p0 = *(const float4*)(&d_prev[pbase + (size_t)(bi + 0) * Nn + nt * 64 + bn]);
            float4 p1 = *(const float4*)(&d_prev[pbase + (size_t)(bi + 1) * Nn + nt * 64 + bn]);
            float4 p2 = *(const float4*)(&d_prev[pbase + (size_t)(bi + 2) * Nn + nt * 64 + bn]);
            float4 p3 = *(const float4*)(&d_prev[pbase + (size_t)(bi + 3) * Nn + nt * 64 + bn]);
            *(float4*)&Pn[(bn + 0) * 68 + bi] = make_float4(p0.x, p1.x, p2.x, p3.x);
            *(float4*)&Pn[(bn + 1) * 68 + bi] = make_float4(p0.y, p1.y, p2.y, p3.y);
            *(float4*)&Pn[(bn + 2) * 68 + bi] = make_float4(p0.z, p1.z, p2.z, p3.z);
            *(float4*)&Pn[(bn + 3) * 68 + bi] = make_float4(p0.w, p1.w, p2.w, p3.w);
        }
        __syncthreads();
#pragma unroll 8
        for (int kk = 0; kk < 64; ++kk) {
            float4 a4 = *(const float4*)&CsT[kk * 68 + ty * 4];
            float4 b4 = *(const float4*)&Pn[kk * 68 + tx * 4];
            float a[4] = {a4.x, a4.y, a4.z, a4.w};
            float b[4] = {b4.x, b4.y, b4.z, b4.w};
#pragma unroll
            for (int i = 0; i < 4; ++i)
#pragma unroll
                for (int j = 0; j < 4; ++j) acc[i][j] += a[i] * b[j];
        }
    }
    const float Dh = Dp[h];
#pragma unroll
    for (int i = 0; i < 4; ++i) {
        int l = li0 + ty * 4 + i;
        float esc = __expf(d_cum[(size_t)l * Hh + h]);
        size_t yi = (size_t)l * INTERC + h * Pp + tx * 4;
        size_t xi = (size_t)l * CONVC + h * Pp + tx * 4;
        float4 yv = *(const float4*)&d_y[yi];
        float4 xv = *(const float4*)&d_xbc[xi];
        yv.x += esc * acc[i][0] + Dh * xv.x;
        yv.y += esc * acc[i][1] + Dh * xv.y;
        yv.z += esc * acc[i][2] + Dh * xv.z;
        yv.w += esc * acc[i][3] + Dh * xv.w;
        *(float4*)&d_y[yi] = yv;
    }
}

// ---------------- gated RMS group-norm (writes fp16 d_gh) ----------------
__global__ void __launch_bounds__(256)
gated_norm_k(const float* __restrict__ norm_w) {
    const int l = blockIdx.x, grp = blockIdx.y;
    const int tid = threadIdx.x;
    float v[4];
    float ss = 0.f;
#pragma unroll
    for (int i = 0; i < 4; ++i) {
        int col = grp * GSZ + tid + i * 256;
        float gate = d_proj[(size_t)l * PROJC + col];
        float yv = d_y[(size_t)l * INTERC + col];
        float sg = gate / (1.f + __expf(-gate));
        v[i] = yv * sg;
        ss += v[i] * v[i];
    }
#pragma unroll
    for (int off = 16; off; off >>= 1) ss += __shfl_xor_sync(0xffffffffu, ss, off);
    __shared__ float red[8];
    if ((tid & 31) == 0) red[tid >> 5] = ss;
    __syncthreads();
    float tot = red[0] + red[1] + red[2] + red[3] + red[4] + red[5] + red[6] + red[7];
    float rs = rsqrtf(tot / (float)GSZ + EPSf);
#pragma unroll
    for (int i = 0; i < 4; ++i) {
        int col = grp * GSZ + tid + i * 256;
        d_gh[(size_t)l * INTERC + col] = __float2half_rn(v[i] * rs * norm_w[col]);
    }
}

// ---------------- launch ----------------
extern "C" void kernel_launch(void* const* d_in, const int* in_sizes, int n_in,
                              void* d_out, int out_size) {
    const float* input     = (const float*)d_in[0];
    const float* in_proj_w = (const float*)d_in[1];
    const float* conv_w    = (const float*)d_in[2];
    const float* conv_b    = (const float*)d_in[3];
    const float* dt_bias   = (const float*)d_in[4];
    const float* A_log     = (const float*)d_in[5];
    const float* Dp        = (const float*)d_in[6];
    const float* norm_w    = (const float*)d_in[7];
    const float* out_w     = (const float*)d_in[8];
    float* out = (float*)d_out;

    cudaFuncSetAttribute(gemm1_mma_k, cudaFuncAttributeMaxDynamicSharedMemorySize, GM_SMEM);
    cudaFuncSetAttribute(gemm2_mma_k, cudaFuncAttributeMaxDynamicSharedMemorySize, GM_SMEM);
    cudaFuncSetAttribute(ssd_intra_k, cudaFuncAttributeMaxDynamicSharedMemorySize, IT_SMEM);

    __half* ha;  cudaGetSymbolAddress((void**)&ha,  d_ha);
    __half* hb1; cudaGetSymbolAddress((void**)&hb1, d_hb1);
    __half* hb2; cudaGetSymbolAddress((void**)&hb2, d_hb2);

    // 0. fp16 pre-converts
    cvt_f16_k<<<(Lq * HIDm / 4 + 255) / 256, 256>>>((const float4*)input, (uint2*)ha, Lq * HIDm / 4);
    cvt_f16_k<<<(PROJC * HIDm / 4 + 255) / 256, 256>>>((const float4*)in_proj_w, (uint2*)hb1, PROJC * HIDm / 4);
    cvt_f16_k<<<(HIDm * INTERC / 4 + 255) / 256, 256>>>((const float4*)out_w, (uint2*)hb2, HIDm * INTERC / 4);

    // 1. in_proj GEMM (fp16 mma): (2048x4096) @ (18560x4096)^T -> d_proj
    gemm1_mma_k<<<dim3(Lq / BMt, PROJC / BNt), 256, GM_SMEM>>>();
    // 2. depthwise causal conv + SiLU -> d_xbc
    conv_silu_k<<<dim3(CONVC / 256, Lq), 256>>>(conv_w, conv_b);
    // 3. dt softplus + per-chunk cumsum(dA)
    dt_cum_k<<<dim3(Hh, NC), 256>>>(dt_bias, A_log);
    // 4. intra-chunk pass -> d_y
    ssd_intra_k<<<dim3(4, Hh, NC), 256, IT_SMEM>>>();
    // 5. per-chunk states
    ssd_states_k<<<dim3(Hh, NC), 256>>>();
    // 6. inter-chunk sequential scan -> d_prev
    ssd_scan_k<<<(Hh * Pp * Nn) / 256, 256>>>();
    // 7. inter-chunk contribution + D*x -> d_y (final)
    ssd_inter_k<<<dim3(4, Hh, NC), 256>>>(Dp);
    // 8. gated RMS group-norm -> d_gh (fp16)
    gated_norm_k<<<dim3(Lq, Gg), 256>>>(norm_w);
    // 9. out GEMM (fp16 mma): (2048x8192) @ (4096x8192)^T -> out
    gemm2_mma_k<<<dim3(Lq / BMt, HIDm / BNt), 256, GM_SMEM>>>(out);
}